// round 15
// baseline (speedup 1.0000x reference)
#include <cuda_runtime.h>
#include <cuda_bf16.h>
#include <math.h>

#define B_ 4
#define S_ 2048
#define D_ 512
#define H_ 8
#define HD 64
#define M_ (B_*S_)
#define EPS_ 1e-5f

typedef unsigned long long ull;

// ---------------------------------------------------------------------------
// Scratch (__device__ globals; allocation-free rule)
// ---------------------------------------------------------------------------
__device__ float g_vin[(size_t)M_*D_];
__device__ float g_att0[(size_t)M_*D_];
__device__ float g_att1[(size_t)M_*D_];
__device__ float g_att2[(size_t)M_*D_];
__device__ float g_att3[(size_t)M_*D_];
__device__ float g_ls0[B_*H_*S_];
__device__ float g_ls1[B_*H_*S_];
__device__ float g_ls2[B_*H_*S_];
__device__ float g_ls3[B_*H_*S_];
__device__ ull g_sqh[M_*D_/4], g_sql[M_*D_/4];
__device__ ull g_skh[M_*D_/4], g_skl[M_*D_/4];
__device__ ull g_svh[M_*D_/4], g_svl[M_*D_/4];
__device__ ull g_w1h[D_*D_/4], g_w1l[D_*D_/4];
__device__ ull g_w2h[D_*D_/4], g_w2l[D_*D_/4];
__device__ ull g_w3h[D_*D_/4], g_w3l[D_*D_/4];
__device__ ull g_qh[M_*D_/4], g_ql[M_*D_/4];
__device__ ull g_kh[M_*D_/4], g_kl[M_*D_/4];
__device__ ull g_vh[M_*D_/4], g_vl[M_*D_/4];

// ---------------------------------------------------------------------------
// helpers
// ---------------------------------------------------------------------------
__device__ __forceinline__ unsigned smem_u32(const void* p) {
    unsigned r;
    asm("{ .reg .u64 t; cvta.to.shared.u64 t, %1; cvt.u32.u64 %0, t; }"
        : "=r"(r) : "l"(p));
    return r;
}
__device__ __forceinline__ void splitpk(float x, float y, unsigned& hp, unsigned& lp) {
    __nv_bfloat16 hx = __float2bfloat16(x), hy = __float2bfloat16(y);
    float rx = x - __bfloat162float(hx), ry = y - __bfloat162float(hy);
    __nv_bfloat16 lx = __float2bfloat16(rx), ly = __float2bfloat16(ry);
    hp = ((unsigned)__bfloat16_as_ushort(hy) << 16) | (unsigned)__bfloat16_as_ushort(hx);
    lp = ((unsigned)__bfloat16_as_ushort(ly) << 16) | (unsigned)__bfloat16_as_ushort(lx);
}
__device__ __forceinline__ ull pkull(unsigned lo32, unsigned hi32) {
    return ((ull)hi32 << 32) | lo32;
}

#define MMA_BF16(c, a, b0, b1) \
    asm volatile("mma.sync.aligned.m16n8k16.row.col.f32.bf16.bf16.f32 " \
        "{%0,%1,%2,%3}, {%4,%5,%6,%7}, {%8,%9}, {%0,%1,%2,%3};" \
        : "+f"((c)[0]), "+f"((c)[1]), "+f"((c)[2]), "+f"((c)[3]) \
        : "r"((a)[0]), "r"((a)[1]), "r"((a)[2]), "r"((a)[3]), "r"(b0), "r"(b1))

#define LDSM4(r0,r1,r2,r3,addr) \
    asm volatile("ldmatrix.sync.aligned.m8n8.x4.shared.b16 {%0,%1,%2,%3}, [%4];" \
        : "=r"(r0),"=r"(r1),"=r"(r2),"=r"(r3) : "r"(addr))
#define LDSM4T(r0,r1,r2,r3,addr) \
    asm volatile("ldmatrix.sync.aligned.m8n8.x4.trans.shared.b16 {%0,%1,%2,%3}, [%4];" \
        : "=r"(r0),"=r"(r1),"=r"(r2),"=r"(r3) : "r"(addr))

__device__ __forceinline__ void cpa16(unsigned sa, const void* ga) {
    asm volatile("cp.async.cg.shared.global [%0], [%1], 16;" :: "r"(sa), "l"(ga) : "memory");
}
#define CPA_COMMIT() asm volatile("cp.async.commit_group;" ::: "memory")
#define CPA_WAIT(n)  asm volatile("cp.async.wait_group %0;" :: "n"(n) : "memory")

#define TSB 144
#define TSK (128*TSB)
#define TSQ (64*TSB)

template<int R>
__device__ __forceinline__ void cpa_tile(unsigned dst, const ull* __restrict__ src,
                                         size_t rowbase, int tid) {
    #pragma unroll
    for (int l = 0; l < R/32; l++) {
        const int idx = tid + l * 256;
        const int r = idx >> 3, c8 = idx & 7;
        cpa16(dst + (unsigned)(r * TSB + c8 * 16), src + rowbase + (size_t)r * 128 + c8 * 2);
    }
}

#define T32B 80
#define TS32 (128*T32B)

__device__ __forceinline__ void cpa_tile32(unsigned dst, const ull* __restrict__ src,
                                           size_t rowbase, int tid) {
    #pragma unroll
    for (int l = 0; l < 2; l++) {
        const int idx = tid + l * 256;
        const int r = idx >> 2, c8 = idx & 3;
        cpa16(dst + (unsigned)(r * T32B + c8 * 16), src + rowbase + (size_t)r * 128 + c8 * 2);
    }
}

// ---------------------------------------------------------------------------
// Merged prologue (unchanged from round 14)
// ---------------------------------------------------------------------------
__device__ __forceinline__ void split4(const float4* __restrict__ x,
                                       ull* __restrict__ hi, ull* __restrict__ lo, int i) {
    float4 v0 = x[i], v1 = x[i+1], v2 = x[i+2], v3 = x[i+3];
    unsigned a,b,c,d;
    ull h[4], l[4];
    splitpk(v0.x, v0.y, a, b); splitpk(v0.z, v0.w, c, d);
    h[0] = pkull(a, c); l[0] = pkull(b, d);
    splitpk(v1.x, v1.y, a, b); splitpk(v1.z, v1.w, c, d);
    h[1] = pkull(a, c); l[1] = pkull(b, d);
    splitpk(v2.x, v2.y, a, b); splitpk(v2.z, v2.w, c, d);
    h[2] = pkull(a, c); l[2] = pkull(b, d);
    splitpk(v3.x, v3.y, a, b); splitpk(v3.z, v3.w, c, d);
    h[3] = pkull(a, c); l[3] = pkull(b, d);
    *(ulonglong2*)&hi[i]   = make_ulonglong2(h[0], h[1]);
    *(ulonglong2*)&hi[i+2] = make_ulonglong2(h[2], h[3]);
    *(ulonglong2*)&lo[i]   = make_ulonglong2(l[0], l[1]);
    *(ulonglong2*)&lo[i+2] = make_ulonglong2(l[2], l[3]);
}

__global__ __launch_bounds__(256) void prologue_kernel(
    const float* __restrict__ seq_v,
    const float* __restrict__ gamma, const float* __restrict__ beta,
    float* __restrict__ vin, ull* __restrict__ svh, ull* __restrict__ svl,
    const float4* __restrict__ xq, ull* __restrict__ sqh, ull* __restrict__ sql,
    const float4* __restrict__ xk, ull* __restrict__ skh, ull* __restrict__ skl,
    const float4* __restrict__ w1, ull* __restrict__ w1h, ull* __restrict__ w1l,
    const float4* __restrict__ w2, ull* __restrict__ w2h, ull* __restrict__ w2l,
    const float4* __restrict__ w3, ull* __restrict__ w3h, ull* __restrict__ w3l)
{
    const int bid = blockIdx.x;
    const int t = threadIdx.x;

    if (bid < 4096) {
        const int row = bid * 2 + (t >> 7);
        const int tid = t & 127;
        const float4* x4 = reinterpret_cast<const float4*>(seq_v + (size_t)row * D_);
        float4 v = x4[tid];
        float s  = v.x + v.y + v.z + v.w;
        float ss = v.x*v.x + v.y*v.y + v.z*v.z + v.w*v.w;
        #pragma unroll
        for (int o = 16; o > 0; o >>= 1) {
            s  += __shfl_xor_sync(0xffffffffu, s,  o);
            ss += __shfl_xor_sync(0xffffffffu, ss, o);
        }
        __shared__ float sb[8], ssb[8];
        const int w = t >> 5;
        if ((t & 31) == 0) { sb[w] = s; ssb[w] = ss; }
        __syncthreads();
        const int wb = (t >> 7) * 4;
        s  = sb[wb+0]  + sb[wb+1]  + sb[wb+2]  + sb[wb+3];
        ss = ssb[wb+0] + ssb[wb+1] + ssb[wb+2] + ssb[wb+3];
        const float mu   = s * (1.0f / D_);
        const float var  = ss * (1.0f / D_) - mu * mu;
        const float rstd = rsqrtf(var + EPS_);
        const float4 g = reinterpret_cast<const float4*>(gamma)[tid];
        const float4 b = reinterpret_cast<const float4*>(beta )[tid];
        float4 o;
        o.x = (v.x - mu) * rstd * g.x + b.x;
        o.y = (v.y - mu) * rstd * g.y + b.y;
        o.z = (v.z - mu) * rstd * g.z + b.z;
        o.w = (v.w - mu) * rstd * g.w + b.w;
        reinterpret_cast<float4*>(vin + (size_t)row * D_)[tid] = o;
        unsigned h01, l01, h23, l23;
        splitpk(o.x, o.y, h01, l01);
        splitpk(o.z, o.w, h23, l23);
        const size_t i = (size_t)row * 128 + tid;
        svh[i] = pkull(h01, h23);
        svl[i] = pkull(l01, l23);
    } else if (bid < 6144) {
        const int n4 = M_ * D_ / 4;
        int i = ((bid - 4096) * 256 + t) * 4;
        if (i < n4) split4(xq, sqh, sql, i);
        else        split4(xk, skh, skl, i - n4);
    } else {
        const int n4 = D_ * D_ / 4;
        int i = ((bid - 6144) * 256 + t) * 4;
        if (i < n4)          split4(w1, w1h, w1l, i);
        else if (i < 2*n4)   split4(w2, w2h, w2l, i - n4);
        else                 split4(w3, w3h, w3l, i - 2*n4);
    }
}

// ---------------------------------------------------------------------------
// Final LN: (O0+O1+O2+O3)/(ls0+ls1+ls2+ls3) + residual, then LN.
// ---------------------------------------------------------------------------
__global__ __launch_bounds__(128) void ln_final_kernel(
    const float* __restrict__ o0, const float* __restrict__ o1,
    const float* __restrict__ o2, const float* __restrict__ o3,
    const float* __restrict__ ls0, const float* __restrict__ ls1,
    const float* __restrict__ ls2, const float* __restrict__ ls3,
    const float* __restrict__ res,
    const float* __restrict__ gamma, const float* __restrict__ beta,
    float* __restrict__ y)
{
    const int row = blockIdx.x;
    const int tid = threadIdx.x;
    const int b  = row >> 11;
    const int i  = row & 2047;
    const int h  = tid >> 4;
    const int li = (b * H_ + h) * S_ + i;
    const float inv = 1.0f / (ls0[li] + ls1[li] + ls2[li] + ls3[li]);

    float4 a0 = reinterpret_cast<const float4*>(o0 + (size_t)row * D_)[tid];
    float4 a1 = reinterpret_cast<const float4*>(o1 + (size_t)row * D_)[tid];
    float4 a2 = reinterpret_cast<const float4*>(o2 + (size_t)row * D_)[tid];
    float4 a3 = reinterpret_cast<const float4*>(o3 + (size_t)row * D_)[tid];
    float4 r  = reinterpret_cast<const float4*>(res + (size_t)row * D_)[tid];
    float4 v;
    v.x = (a0.x + a1.x + a2.x + a3.x) * inv + r.x;
    v.y = (a0.y + a1.y + a2.y + a3.y) * inv + r.y;
    v.z = (a0.z + a1.z + a2.z + a3.z) * inv + r.z;
    v.w = (a0.w + a1.w + a2.w + a3.w) * inv + r.w;

    float s  = v.x + v.y + v.z + v.w;
    float ss = v.x*v.x + v.y*v.y + v.z*v.z + v.w*v.w;
    #pragma unroll
    for (int o = 16; o > 0; o >>= 1) {
        s  += __shfl_xor_sync(0xffffffffu, s,  o);
        ss += __shfl_xor_sync(0xffffffffu, ss, o);
    }
    __shared__ float sb[4], ssb[4];
    const int w = tid >> 5;
    if ((tid & 31) == 0) { sb[w] = s; ssb[w] = ss; }
    __syncthreads();
    s  = sb[0]  + sb[1]  + sb[2]  + sb[3];
    ss = ssb[0] + ssb[1] + ssb[2] + ssb[3];
    const float mu   = s * (1.0f / D_);
    const float var  = ss * (1.0f / D_) - mu * mu;
    const float rstd = rsqrtf(var + EPS_);
    const float4 g = reinterpret_cast<const float4*>(gamma)[tid];
    const float4 bb = reinterpret_cast<const float4*>(beta )[tid];
    float4 o;
    o.x = (v.x - mu) * rstd * g.x + bb.x;
    o.y = (v.y - mu) * rstd * g.y + bb.y;
    o.z = (v.z - mu) * rstd * g.z + bb.z;
    o.w = (v.w - mu) * rstd * g.w + bb.w;
    reinterpret_cast<float4*>(y + (size_t)row * D_)[tid] = o;
}

// ---------------------------------------------------------------------------
// HMMA NT GEMM, 3-in-1. (Frozen.)
// ---------------------------------------------------------------------------
#define GB32(buf) ((unsigned)((buf) * 4 * TS32))
#define G_AH 0
#define G_AL TS32
#define G_WH (2*TS32)
#define G_WL (3*TS32)
#define GEMM_SMEM (8*TS32)

__global__ __launch_bounds__(256, 2) void gemm_tc(
    const ull* __restrict__ A0h, const ull* __restrict__ A0l,
    const ull* __restrict__ W0h, const ull* __restrict__ W0l,
    __nv_bfloat16* __restrict__ C0h, __nv_bfloat16* __restrict__ C0l,
    const ull* __restrict__ A1h, const ull* __restrict__ A1l,
    const ull* __restrict__ W1h_, const ull* __restrict__ W1l_,
    __nv_bfloat16* __restrict__ C1h, __nv_bfloat16* __restrict__ C1l,
    const ull* __restrict__ A2h, const ull* __restrict__ A2l,
    const ull* __restrict__ W2h_, const ull* __restrict__ W2l_,
    __nv_bfloat16* __restrict__ C2h, __nv_bfloat16* __restrict__ C2l)
{
    const ull *Ah, *Al, *Wh, *Wl;
    __nv_bfloat16 *Ch, *Cl;
    if (blockIdx.z == 0)      { Ah=A0h; Al=A0l; Wh=W0h;  Wl=W0l;  Ch=C0h; Cl=C0l; }
    else if (blockIdx.z == 1) { Ah=A1h; Al=A1l; Wh=W1h_; Wl=W1l_; Ch=C1h; Cl=C1l; }
    else                      { Ah=A2h; Al=A2l; Wh=W2h_; Wl=W2l_; Ch=C2h; Cl=C2l; }

    extern __shared__ char smc[];
    const unsigned sbase = smem_u32(smc);
    const int tid = threadIdx.x;
    const int lane = tid & 31;
    const int w = tid >> 5;
    const int wm = w >> 2;
    const int wn = w & 3;
    const int m0 = blockIdx.y * 128;
    const int n0 = blockIdx.x * 128;

    float Ca[16][4];
    #pragma unroll
    for (int nb = 0; nb < 16; nb++)
        #pragma unroll
        for (int r = 0; r < 4; r++) Ca[nb][r] = 0.f;

    const unsigned a_off = (unsigned)((lane & 15) * T32B + (lane >> 4) * 16 + wm * 64 * T32B);
    const unsigned b_off = (unsigned)((((lane >> 4) * 8) + (lane & 7)) * T32B + ((lane >> 3) & 1) * 16
                                      + wn * 32 * T32B);

    const size_t abase = (size_t)m0 * 128;
    const size_t wbase = (size_t)n0 * 128;

    cpa_tile32(sbase + GB32(0) + G_AH, Ah, abase, tid);
    cpa_tile32(sbase + GB32(0) + G_AL, Al, abase, tid);
    cpa_tile32(sbase + GB32(0) + G_WH, Wh, wbase, tid);
    cpa_tile32(sbase + GB32(0) + G_WL, Wl, wbase, tid);
    CPA_COMMIT();

    for (int c = 0; c < 16; c++) {
        if (c < 15) {
            const unsigned nb_ = GB32((c + 1) & 1);
            const size_t ab = abase + (c + 1) * 8;
            const size_t wb = wbase + (c + 1) * 8;
            cpa_tile32(sbase + nb_ + G_AH, Ah, ab, tid);
            cpa_tile32(sbase + nb_ + G_AL, Al, ab, tid);
            cpa_tile32(sbase + nb_ + G_WH, Wh, wb, tid);
            cpa_tile32(sbase + nb_ + G_WL, Wl, wb, tid);
            CPA_COMMIT();
            CPA_WAIT(1);
        } else {
            CPA_WAIT(0);
        }
        __syncthreads();

        const unsigned cb = GB32(c & 1);
        #pragma unroll
        for (int ks = 0; ks < 2; ks++) {
            unsigned ah[4][4], al4[4][4];
            #pragma unroll
            for (int mb = 0; mb < 4; mb++) {
                LDSM4(ah[mb][0], ah[mb][1], ah[mb][2], ah[mb][3],
                      sbase + cb + G_AH + a_off + (unsigned)(mb*16*T32B) + ks*32);
                LDSM4(al4[mb][0], al4[mb][1], al4[mb][2], al4[mb][3],
                      sbase + cb + G_AL + a_off + (unsigned)(mb*16*T32B) + ks*32);
            }
            #pragma unroll
            for (int nb16 = 0; nb16 < 2; nb16++) {
                unsigned bh0,bh1,bh2,bh3, bl0,bl1,bl2,bl3;
                LDSM4(bh0,bh1,bh2,bh3, sbase + cb + G_WH + b_off + (unsigned)(nb16*16*T32B) + ks*32);
                LDSM4(bl0,bl1,bl2,bl3, sbase + cb + G_WL + b_off + (unsigned)(nb16*16*T32B) + ks*32);
                #pragma unroll
                for (int mb = 0; mb < 4; mb++) {
                    MMA_BF16(Ca[mb*4 + nb16*2],     ah[mb], bh0, bh1);
                    MMA_BF16(Ca[mb*4 + nb16*2 + 1], ah[mb], bh2, bh3);
                }
                #pragma unroll
                for (int mb = 0; mb < 4; mb++) {
                    MMA_BF16(Ca[mb*4 + nb16*2],     ah[mb], bl0, bl1);
                    MMA_BF16(Ca[mb*4 + nb16*2 + 1], ah[mb], bl2, bl3);
                }
                #pragma unroll
                for (int mb = 0; mb < 4; mb++) {
                    MMA_BF16(Ca[mb*4 + nb16*2],     al4[mb], bh0, bh1);
                    MMA_BF16(Ca[mb*4 + nb16*2 + 1], al4[mb], bh2, bh3);
                }
            }
        }
        __syncthreads();
    }

    const int g = lane >> 2, t = lane & 3;
    #pragma unroll
    for (int mb = 0; mb < 4; mb++) {
        const int r0 = m0 + wm * 64 + mb * 16 + g;
        const int r1 = r0 + 8;
        #pragma unroll
        for (int nbu = 0; nbu < 4; nbu++) {
            const int col = n0 + wn * 32 + nbu * 8 + 2 * t;
            unsigned h01, l01, h23, l23;
            splitpk(Ca[mb*4+nbu][0], Ca[mb*4+nbu][1], h01, l01);
            splitpk(Ca[mb*4+nbu][2], Ca[mb*4+nbu][3], h23, l23);
            *(unsigned*)&Ch[(size_t)r0 * D_ + col] = h01;
            *(unsigned*)&Cl[(size_t)r0 * D_ + col] = l01;
            *(unsigned*)&Ch[(size_t)r1 * D_ + col] = h23;
            *(unsigned*)&Cl[(size_t)r1 * D_ + col] = l23;
        }
    }
}

// ---------------------------------------------------------------------------
// HMMA attention: NO-MAX softmax, 4-WAY j-split (blockIdx.z = quarter, NJT=8).
// BJ=64 double-buffered cp.async, 2 CTAs/SM, K register-persistent.
// ---------------------------------------------------------------------------
#define AQV(buf, t) (2*TSK + (buf)*4*TSQ + (t)*TSQ)
#define ATTN_SMEM (2*TSK + 8*TSQ)
#define NJT 8

__global__ __launch_bounds__(256, 2) void attn_tc(
    const ull* __restrict__ Qh, const ull* __restrict__ Ql,
    const ull* __restrict__ Kh, const ull* __restrict__ Kl,
    const ull* __restrict__ Vh, const ull* __restrict__ Vl,
    float* __restrict__ O0, float* __restrict__ O1,
    float* __restrict__ O2, float* __restrict__ O3,
    float* __restrict__ LS0, float* __restrict__ LS1,
    float* __restrict__ LS2, float* __restrict__ LS3)
{
    extern __shared__ char smc[];
    const unsigned sbase = smem_u32(smc);
    const int tid = threadIdx.x;
    const int lane = tid & 31;
    const int w = tid >> 5;
    const int it = blockIdx.x;
    const int bh = blockIdx.y;
    const int qz = blockIdx.z;
    float* __restrict__ Op  = (qz == 0) ? O0  : (qz == 1) ? O1  : (qz == 2) ? O2  : O3;
    float* __restrict__ LSp = (qz == 0) ? LS0 : (qz == 1) ? LS1 : (qz == 2) ? LS2 : LS3;
    const int b = bh >> 3, h = bh & 7;
    const size_t base = (size_t)b * S_ * D_ + (size_t)h * HD;
    const size_t base4 = base >> 2;
    const int i0 = it * 128;
    const int jt0 = qz * NJT;

    cpa_tile<128>(sbase + 0*TSK, Kh, base4 + (size_t)i0 * 128, tid);
    cpa_tile<128>(sbase + 1*TSK, Kl, base4 + (size_t)i0 * 128, tid);
    CPA_COMMIT();
    cpa_tile<64>(sbase + AQV(0,0), Qh, base4 + (size_t)jt0 * 64 * 128, tid);
    cpa_tile<64>(sbase + AQV(0,1), Ql, base4 + (size_t)jt0 * 64 * 128, tid);
    cpa_tile<64>(sbase + AQV(0,2), Vh, base4 + (size_t)jt0 * 64 * 128, tid);
    cpa_tile<64>(sbase + AQV(0,3), Vl, base4 + (size_t)jt0 * 64 * 128, tid);
    CPA_COMMIT();
    CPA_WAIT(1);
    __syncthreads();

    const unsigned a_off = (unsigned)((lane & 15) * TSB + (lane >> 4) * 16) + (unsigned)(w * 16 * TSB);
    unsigned kha[4][4], kla[4][4];
    #pragma unroll
    for (int ks = 0; ks < 4; ks++) {
        LDSM4(kha[ks][0], kha[ks][1], kha[ks][2], kha[ks][3], sbase + 0*TSK + a_off + ks*32);
        LDSM4(kla[ks][0], kla[ks][1], kla[ks][2], kla[ks][3], sbase + 1*TSK + a_off + ks*32);
    }

    const unsigned b_off = (unsigned)((((lane >> 4) * 8) + (lane & 7)) * TSB + ((lane >> 3) & 1) * 16);
    const unsigned v_off = (unsigned)(((((lane >> 3) & 1) * 8) + (lane & 7)) * TSB + (lane >> 4) * 16);

    float Oa[8][4];
    #pragma unroll
    for (int db = 0; db < 8; db++)
        #pragma unroll
        for (int r = 0; r < 4; r++) Oa[db][r] = 0.f;
    float lsum0 = 0.f, lsum1 = 0.f;

    for (int jt = 0; jt < NJT; jt++) {
        if (jt < NJT-1) {
            const int nb_ = (jt + 1) & 1;
            const size_t rb = base4 + (size_t)(jt0 + jt + 1) * 64 * 128;
            cpa_tile<64>(sbase + AQV(nb_,0), Qh, rb, tid);
            cpa_tile<64>(sbase + AQV(nb_,1), Ql, rb, tid);
            cpa_tile<64>(sbase + AQV(nb_,2), Vh, rb, tid);
            cpa_tile<64>(sbase + AQV(nb_,3), Vl, rb, tid);
            CPA_COMMIT();
            CPA_WAIT(1);
        } else {
            CPA_WAIT(0);
        }
        __syncthreads();

        const int bb = jt & 1;
        const unsigned qh_b = sbase + AQV(bb,0);
        const unsigned ql_b = sbase + AQV(bb,1);
        const unsigned vh_b = sbase + AQV(bb,2);
        const unsigned vl_b = sbase + AQV(bb,3);

        float Sa[8][4];
        #pragma unroll
        for (int nb = 0; nb < 8; nb++)
            #pragma unroll
            for (int r = 0; r < 4; r++) Sa[nb][r] = 0.f;

        #pragma unroll
        for (int jp = 0; jp < 2; jp++) {
            #pragma unroll
            for (int ks = 0; ks < 4; ks++) {
                unsigned bh2[2][4], bl2[2][4];
                #pragma unroll
                for (int j = 0; j < 2; j++) {
                    LDSM4(bh2[j][0],bh2[j][1],bh2[j][2],bh2[j][3],
                          qh_b + (unsigned)((jp*2+j)*16*TSB) + ks*32 + b_off);
                    LDSM4(bl2[j][0],bl2[j][1],bl2[j][2],bl2[j][3],
                          ql_b + (unsigned)((jp*2+j)*16*TSB) + ks*32 + b_off);
                }
                #pragma unroll
                for (int j = 0; j < 2; j++) {
                    MMA_BF16(Sa[4*jp+2*j],   kha[ks], bh2[j][0], bh2[j][1]);
                    MMA_BF16(Sa[4*jp+2*j+1], kha[ks], bh2[j][2], bh2[j][3]);
                }
                #pragma unroll
                for (int j = 0; j < 2; j++) {
                    MMA_BF16(Sa[4*jp+2*j],   kha[ks], bl2[j][0], bl2[j][1]);
                    MMA_BF16(Sa[4*jp+2*j+1], kha[ks], bl2[j][2], bl2[j][3]);
                }
                #pragma unroll
                for (int j = 0; j < 2; j++) {
                    MMA_BF16(Sa[4*jp+2*j],   kla[ks], bh2[j][0], bh2[j][1]);
                    MMA_BF16(Sa[4*jp+2*j+1], kla[ks], bh2[j][2], bh2[j][3]);
                }
            }
        }

        float rs0 = 0.f, rs1 = 0.f;
        #pragma unroll
        for (int nb = 0; nb < 8; nb++) {
            Sa[nb][0] = __expf(Sa[nb][0]);
            Sa[nb][1] = __expf(Sa[nb][1]);
            Sa[nb][2] = __expf(Sa[nb][2]);
            Sa[nb][3] = __expf(Sa[nb][3]);
            rs0 += Sa[nb][0] + Sa[nb][1];
            rs1 += Sa[nb][2] + Sa[nb][3];
        }

        unsigned pah[4][4], pal[4][4];
        #pragma unroll
        for (int ks = 0; ks < 4; ks++) {
            splitpk(Sa[2*ks][0],   Sa[2*ks][1],   pah[ks][0], pal[ks][0]);
            splitpk(Sa[2*ks][2],   Sa[2*ks][3],   pah[ks][1], pal[ks][1]);
            splitpk(Sa[2*ks+1][0], Sa[2*ks+1][1], pah[ks][2], pal[ks][2]);
            splitpk(Sa[2*ks+1][2], Sa[2*ks+1][3], pah[ks][3], pal[ks][3]);
        }

        #pragma unroll
        for (int ks = 0; ks < 4; ks++) {
            #pragma unroll
            for (int dp = 0; dp < 2; dp++) {
                unsigned vh[2][4], vl[2][4];
                #pragma unroll
                for (int d = 0; d < 2; d++) {
                    LDSM4T(vh[d][0],vh[d][1],vh[d][2],vh[d][3],
                           vh_b + (unsigned)(ks*16*TSB) + (dp*2+d)*32 + v_off);
                    LDSM4T(vl[d][0],vl[d][1],vl[d][2],vl[d][3],
                           vl_b + (unsigned)(ks*16*TSB) + (dp*2+d)*32 + v_off);
                }
                #pragma unroll
                for (int d = 0; d < 2; d++) {
                    MMA_BF16(Oa[4*dp+2*d],   pah[ks], vh[d][0], vh[d][1]);
                    MMA_BF16(Oa[4*dp+2*d+1], pah[ks], vh[d][2], vh[d][3]);
                }
                #pragma unroll
                for (int d = 0; d < 2; d++) {
                    MMA_BF16(Oa[4*dp+2*d],   pah[ks], vl[d][0], vl[d][1]);
                    MMA_BF16(Oa[4*dp+2*d+1], pah[ks], vl[d][2], vl[d][3]);
                }
                #pragma unroll
                for (int d = 0; d < 2; d++) {
                    MMA_BF16(Oa[4*dp+2*d],   pal[ks], vh[d][0], vh[d][1]);
                    MMA_BF16(Oa[4*dp+2*d+1], pal[ks], vh[d][2], vh[d][3]);
                }
            }
        }

        rs0 += __shfl_xor_sync(0xffffffffu, rs0, 1);
        rs0 += __shfl_xor_sync(0xffffffffu, rs0, 2);
        rs1 += __shfl_xor_sync(0xffffffffu, rs1, 1);
        rs1 += __shfl_xor_sync(0xffffffffu, rs1, 2);
        lsum0 += rs0;
        lsum1 += rs1;
        __syncthreads();
    }

    const int g = lane >> 2, t = lane & 3;
    const int r0 = i0 + w * 16 + g;
    const int r1 = r0 + 8;
    #pragma unroll
    for (int db = 0; db < 8; db++) {
        const int col = db * 8 + 2 * t;
        *(float2*)&Op[base + (size_t)r0 * D_ + col] = make_float2(Oa[db][0], Oa[db][1]);
        *(float2*)&Op[base + (size_t)r1 * D_ + col] = make_float2(Oa[db][2], Oa[db][3]);
    }
    if (t == 0) {
        LSp[bh * S_ + r0] = lsum0;
        LSp[bh * S_ + r1] = lsum1;
    }
}

// ---------------------------------------------------------------------------
extern "C" void kernel_launch(void* const* d_in, const int* in_sizes, int n_in,
                              void* d_out, int out_size)
{
    const float* seq_k = (const float*)d_in[0];
    const float* seq_q = (const float*)d_in[1];
    const float* seq_v = (const float*)d_in[2];
    const float* W1    = (const float*)d_in[3];
    const float* W2    = (const float*)d_in[4];
    const float* W3    = (const float*)d_in[5];
    const float* gamma = (const float*)d_in[6];
    const float* beta  = (const float*)d_in[7];
    float* out = (float*)d_out;

    float *vin, *att0, *att1, *att2, *att3, *ls0, *ls1, *ls2, *ls3;
    ull *sqh,*sql,*skh,*skl,*svh,*svl,*w1h,*w1l,*w2h,*w2l,*w3h,*w3l;
    ull *qh,*ql,*kh,*kl,*vh,*vl;
    cudaGetSymbolAddress((void**)&vin,  g_vin);
    cudaGetSymbolAddress((void**)&att0, g_att0);
    cudaGetSymbolAddress((void**)&att1, g_att1);
    cudaGetSymbolAddress((void**)&att2, g_att2);
    cudaGetSymbolAddress((void**)&att3, g_att3);
    cudaGetSymbolAddress((void**)&ls0,  g_ls0);
    cudaGetSymbolAddress((void**)&ls1,  g_ls1);
    cudaGetSymbolAddress((void**)&ls2,  g_ls2);
    cudaGetSymbolAddress((void**)&ls3,  g_ls3);
    cudaGetSymbolAddress((void**)&sqh, g_sqh); cudaGetSymbolAddress((void**)&sql, g_sql);
    cudaGetSymbolAddress((void**)&skh, g_skh); cudaGetSymbolAddress((void**)&skl, g_skl);
    cudaGetSymbolAddress((void**)&svh, g_svh); cudaGetSymbolAddress((void**)&svl, g_svl);
    cudaGetSymbolAddress((void**)&w1h, g_w1h); cudaGetSymbolAddress((void**)&w1l, g_w1l);
    cudaGetSymbolAddress((void**)&w2h, g_w2h); cudaGetSymbolAddress((void**)&w2l, g_w2l);
    cudaGetSymbolAddress((void**)&w3h, g_w3h); cudaGetSymbolAddress((void**)&w3l, g_w3l);
    cudaGetSymbolAddress((void**)&qh,  g_qh);  cudaGetSymbolAddress((void**)&ql,  g_ql);
    cudaGetSymbolAddress((void**)&kh,  g_kh);  cudaGetSymbolAddress((void**)&kl,  g_kl);
    cudaGetSymbolAddress((void**)&vh,  g_vh);  cudaGetSymbolAddress((void**)&vl,  g_vl);

    // 1) merged prologue
    prologue_kernel<<<6336, 256>>>(
        seq_v, gamma, beta, vin, svh, svl,
        (const float4*)seq_q, sqh, sql,
        (const float4*)seq_k, skh, skl,
        (const float4*)W1, w1h, w1l,
        (const float4*)W2, w2h, w2l,
        (const float4*)W3, w3h, w3l);

    // 2) projections
    cudaFuncSetAttribute(gemm_tc, cudaFuncAttributeMaxDynamicSharedMemorySize, GEMM_SMEM);
    dim3 ggrid(D_ / 128, M_ / 128, 3);
    gemm_tc<<<ggrid, 256, GEMM_SMEM>>>(
        sqh, sql, w1h, w1l, (__nv_bfloat16*)qh, (__nv_bfloat16*)ql,
        skh, skl, w2h, w2l, (__nv_bfloat16*)kh, (__nv_bfloat16*)kl,
        svh, svl, w3h, w3l, (__nv_bfloat16*)vh, (__nv_bfloat16*)vl);

    // 3) attention (4-way j-split)
    cudaFuncSetAttribute(attn_tc, cudaFuncAttributeMaxDynamicSharedMemorySize, ATTN_SMEM);
    attn_tc<<<dim3(S_ / 128, B_ * H_, 4), 256, ATTN_SMEM>>>(
        qh, ql, kh, kl, vh, vl,
        att0, att1, att2, att3, ls0, ls1, ls2, ls3);

    // 4) combine + residual + final LN
    ln_final_kernel<<<M_, 128>>>(att0, att1, att2, att3,
                                 ls0, ls1, ls2, ls3, vin, gamma, beta, out);
}

// round 16
// speedup vs baseline: 1.0193x; 1.0193x over previous
#include <cuda_runtime.h>
#include <cuda_bf16.h>
#include <math.h>

#define B_ 4
#define S_ 2048
#define D_ 512
#define H_ 8
#define HD 64
#define M_ (B_*S_)
#define EPS_ 1e-5f

typedef unsigned long long ull;

// ---------------------------------------------------------------------------
// Scratch (__device__ globals; allocation-free rule)
// ---------------------------------------------------------------------------
__device__ float g_vin[(size_t)M_*D_];
__device__ float g_att0[(size_t)M_*D_];
__device__ float g_att1[(size_t)M_*D_];
__device__ float g_ls0[B_*H_*S_];
__device__ float g_ls1[B_*H_*S_];
__device__ ull g_sqh[M_*D_/4], g_sql[M_*D_/4];
__device__ ull g_skh[M_*D_/4], g_skl[M_*D_/4];
__device__ ull g_svh[M_*D_/4], g_svl[M_*D_/4];
__device__ ull g_w1h[D_*D_/4], g_w1l[D_*D_/4];
__device__ ull g_w2h[D_*D_/4], g_w2l[D_*D_/4];
__device__ ull g_w3h[D_*D_/4], g_w3l[D_*D_/4];
__device__ ull g_qh[M_*D_/4], g_ql[M_*D_/4];
__device__ ull g_kh[M_*D_/4], g_kl[M_*D_/4];
__device__ ull g_vh[M_*D_/4], g_vl[M_*D_/4];

// ---------------------------------------------------------------------------
// helpers
// ---------------------------------------------------------------------------
__device__ __forceinline__ unsigned smem_u32(const void* p) {
    unsigned r;
    asm("{ .reg .u64 t; cvta.to.shared.u64 t, %1; cvt.u32.u64 %0, t; }"
        : "=r"(r) : "l"(p));
    return r;
}
__device__ __forceinline__ void splitpk(float x, float y, unsigned& hp, unsigned& lp) {
    __nv_bfloat16 hx = __float2bfloat16(x), hy = __float2bfloat16(y);
    float rx = x - __bfloat162float(hx), ry = y - __bfloat162float(hy);
    __nv_bfloat16 lx = __float2bfloat16(rx), ly = __float2bfloat16(ry);
    hp = ((unsigned)__bfloat16_as_ushort(hy) << 16) | (unsigned)__bfloat16_as_ushort(hx);
    lp = ((unsigned)__bfloat16_as_ushort(ly) << 16) | (unsigned)__bfloat16_as_ushort(lx);
}
__device__ __forceinline__ ull pkull(unsigned lo32, unsigned hi32) {
    return ((ull)hi32 << 32) | lo32;
}

#define MMA_BF16(c, a, b0, b1) \
    asm volatile("mma.sync.aligned.m16n8k16.row.col.f32.bf16.bf16.f32 " \
        "{%0,%1,%2,%3}, {%4,%5,%6,%7}, {%8,%9}, {%0,%1,%2,%3};" \
        : "+f"((c)[0]), "+f"((c)[1]), "+f"((c)[2]), "+f"((c)[3]) \
        : "r"((a)[0]), "r"((a)[1]), "r"((a)[2]), "r"((a)[3]), "r"(b0), "r"(b1))

#define LDSM4(r0,r1,r2,r3,addr) \
    asm volatile("ldmatrix.sync.aligned.m8n8.x4.shared.b16 {%0,%1,%2,%3}, [%4];" \
        : "=r"(r0),"=r"(r1),"=r"(r2),"=r"(r3) : "r"(addr))
#define LDSM4T(r0,r1,r2,r3,addr) \
    asm volatile("ldmatrix.sync.aligned.m8n8.x4.trans.shared.b16 {%0,%1,%2,%3}, [%4];" \
        : "=r"(r0),"=r"(r1),"=r"(r2),"=r"(r3) : "r"(addr))

__device__ __forceinline__ void cpa16(unsigned sa, const void* ga) {
    asm volatile("cp.async.cg.shared.global [%0], [%1], 16;" :: "r"(sa), "l"(ga) : "memory");
}
#define CPA_COMMIT() asm volatile("cp.async.commit_group;" ::: "memory")
#define CPA_WAIT(n)  asm volatile("cp.async.wait_group %0;" :: "n"(n) : "memory")

#define TSB 144
#define TSK (128*TSB)
#define TSQ (64*TSB)

template<int R>
__device__ __forceinline__ void cpa_tile(unsigned dst, const ull* __restrict__ src,
                                         size_t rowbase, int tid) {
    #pragma unroll
    for (int l = 0; l < R/32; l++) {
        const int idx = tid + l * 256;
        const int r = idx >> 3, c8 = idx & 7;
        cpa16(dst + (unsigned)(r * TSB + c8 * 16), src + rowbase + (size_t)r * 128 + c8 * 2);
    }
}

#define T32B 80
#define TS32 (128*T32B)

__device__ __forceinline__ void cpa_tile32(unsigned dst, const ull* __restrict__ src,
                                           size_t rowbase, int tid) {
    #pragma unroll
    for (int l = 0; l < 2; l++) {
        const int idx = tid + l * 256;
        const int r = idx >> 2, c8 = idx & 3;
        cpa16(dst + (unsigned)(r * T32B + c8 * 16), src + rowbase + (size_t)r * 128 + c8 * 2);
    }
}

// ---------------------------------------------------------------------------
// Merged prologue (round-14 exact)
// ---------------------------------------------------------------------------
__device__ __forceinline__ void split4(const float4* __restrict__ x,
                                       ull* __restrict__ hi, ull* __restrict__ lo, int i) {
    float4 v0 = x[i], v1 = x[i+1], v2 = x[i+2], v3 = x[i+3];
    unsigned a,b,c,d;
    ull h[4], l[4];
    splitpk(v0.x, v0.y, a, b); splitpk(v0.z, v0.w, c, d);
    h[0] = pkull(a, c); l[0] = pkull(b, d);
    splitpk(v1.x, v1.y, a, b); splitpk(v1.z, v1.w, c, d);
    h[1] = pkull(a, c); l[1] = pkull(b, d);
    splitpk(v2.x, v2.y, a, b); splitpk(v2.z, v2.w, c, d);
    h[2] = pkull(a, c); l[2] = pkull(b, d);
    splitpk(v3.x, v3.y, a, b); splitpk(v3.z, v3.w, c, d);
    h[3] = pkull(a, c); l[3] = pkull(b, d);
    *(ulonglong2*)&hi[i]   = make_ulonglong2(h[0], h[1]);
    *(ulonglong2*)&hi[i+2] = make_ulonglong2(h[2], h[3]);
    *(ulonglong2*)&lo[i]   = make_ulonglong2(l[0], l[1]);
    *(ulonglong2*)&lo[i+2] = make_ulonglong2(l[2], l[3]);
}

__global__ __launch_bounds__(256) void prologue_kernel(
    const float* __restrict__ seq_v,
    const float* __restrict__ gamma, const float* __restrict__ beta,
    float* __restrict__ vin, ull* __restrict__ svh, ull* __restrict__ svl,
    const float4* __restrict__ xq, ull* __restrict__ sqh, ull* __restrict__ sql,
    const float4* __restrict__ xk, ull* __restrict__ skh, ull* __restrict__ skl,
    const float4* __restrict__ w1, ull* __restrict__ w1h, ull* __restrict__ w1l,
    const float4* __restrict__ w2, ull* __restrict__ w2h, ull* __restrict__ w2l,
    const float4* __restrict__ w3, ull* __restrict__ w3h, ull* __restrict__ w3l)
{
    const int bid = blockIdx.x;
    const int t = threadIdx.x;

    if (bid < 4096) {
        const int row = bid * 2 + (t >> 7);
        const int tid = t & 127;
        const float4* x4 = reinterpret_cast<const float4*>(seq_v + (size_t)row * D_);
        float4 v = x4[tid];
        float s  = v.x + v.y + v.z + v.w;
        float ss = v.x*v.x + v.y*v.y + v.z*v.z + v.w*v.w;
        #pragma unroll
        for (int o = 16; o > 0; o >>= 1) {
            s  += __shfl_xor_sync(0xffffffffu, s,  o);
            ss += __shfl_xor_sync(0xffffffffu, ss, o);
        }
        __shared__ float sb[8], ssb[8];
        const int w = t >> 5;
        if ((t & 31) == 0) { sb[w] = s; ssb[w] = ss; }
        __syncthreads();
        const int wb = (t >> 7) * 4;
        s  = sb[wb+0]  + sb[wb+1]  + sb[wb+2]  + sb[wb+3];
        ss = ssb[wb+0] + ssb[wb+1] + ssb[wb+2] + ssb[wb+3];
        const float mu   = s * (1.0f / D_);
        const float var  = ss * (1.0f / D_) - mu * mu;
        const float rstd = rsqrtf(var + EPS_);
        const float4 g = reinterpret_cast<const float4*>(gamma)[tid];
        const float4 b = reinterpret_cast<const float4*>(beta )[tid];
        float4 o;
        o.x = (v.x - mu) * rstd * g.x + b.x;
        o.y = (v.y - mu) * rstd * g.y + b.y;
        o.z = (v.z - mu) * rstd * g.z + b.z;
        o.w = (v.w - mu) * rstd * g.w + b.w;
        reinterpret_cast<float4*>(vin + (size_t)row * D_)[tid] = o;
        unsigned h01, l01, h23, l23;
        splitpk(o.x, o.y, h01, l01);
        splitpk(o.z, o.w, h23, l23);
        const size_t i = (size_t)row * 128 + tid;
        svh[i] = pkull(h01, h23);
        svl[i] = pkull(l01, l23);
    } else if (bid < 6144) {
        const int n4 = M_ * D_ / 4;
        int i = ((bid - 4096) * 256 + t) * 4;
        if (i < n4) split4(xq, sqh, sql, i);
        else        split4(xk, skh, skl, i - n4);
    } else {
        const int n4 = D_ * D_ / 4;
        int i = ((bid - 6144) * 256 + t) * 4;
        if (i < n4)          split4(w1, w1h, w1l, i);
        else if (i < 2*n4)   split4(w2, w2h, w2l, i - n4);
        else                 split4(w3, w3h, w3l, i - 2*n4);
    }
}

// ---------------------------------------------------------------------------
// Final LN: 2 rows per 256-thread block (better MLP/issue than 1 row x 128).
// (O0+O1)/(ls0+ls1) + residual, then LN.
// ---------------------------------------------------------------------------
__global__ __launch_bounds__(256) void ln_final_kernel(
    const float* __restrict__ o0, const float* __restrict__ o1,
    const float* __restrict__ ls0, const float* __restrict__ ls1,
    const float* __restrict__ res,
    const float* __restrict__ gamma, const float* __restrict__ beta,
    float* __restrict__ y)
{
    const int t = threadIdx.x;
    const int row = blockIdx.x * 2 + (t >> 7);   // b*S + i
    const int tid = t & 127;
    const int b  = row >> 11;
    const int i  = row & 2047;
    const int h  = tid >> 4;
    const int li = (b * H_ + h) * S_ + i;
    const float inv = 1.0f / (ls0[li] + ls1[li]);

    float4 a0 = reinterpret_cast<const float4*>(o0 + (size_t)row * D_)[tid];
    float4 a1 = reinterpret_cast<const float4*>(o1 + (size_t)row * D_)[tid];
    float4 r  = reinterpret_cast<const float4*>(res + (size_t)row * D_)[tid];
    float4 v;
    v.x = (a0.x + a1.x) * inv + r.x;
    v.y = (a0.y + a1.y) * inv + r.y;
    v.z = (a0.z + a1.z) * inv + r.z;
    v.w = (a0.w + a1.w) * inv + r.w;

    float s  = v.x + v.y + v.z + v.w;
    float ss = v.x*v.x + v.y*v.y + v.z*v.z + v.w*v.w;
    #pragma unroll
    for (int o = 16; o > 0; o >>= 1) {
        s  += __shfl_xor_sync(0xffffffffu, s,  o);
        ss += __shfl_xor_sync(0xffffffffu, ss, o);
    }
    __shared__ float sb[8], ssb[8];
    const int w = t >> 5;
    if ((t & 31) == 0) { sb[w] = s; ssb[w] = ss; }
    __syncthreads();
    const int wb = (t >> 7) * 4;
    s  = sb[wb+0]  + sb[wb+1]  + sb[wb+2]  + sb[wb+3];
    ss = ssb[wb+0] + ssb[wb+1] + ssb[wb+2] + ssb[wb+3];
    const float mu   = s * (1.0f / D_);
    const float var  = ss * (1.0f / D_) - mu * mu;
    const float rstd = rsqrtf(var + EPS_);
    const float4 g = reinterpret_cast<const float4*>(gamma)[tid];
    const float4 bb = reinterpret_cast<const float4*>(beta )[tid];
    float4 o;
    o.x = (v.x - mu) * rstd * g.x + bb.x;
    o.y = (v.y - mu) * rstd * g.y + bb.y;
    o.z = (v.z - mu) * rstd * g.z + bb.z;
    o.w = (v.w - mu) * rstd * g.w + bb.w;
    reinterpret_cast<float4*>(y + (size_t)row * D_)[tid] = o;
}

// ---------------------------------------------------------------------------
// HMMA NT GEMM, 3-in-1. (Frozen.)
// ---------------------------------------------------------------------------
#define GB32(buf) ((unsigned)((buf) * 4 * TS32))
#define G_AH 0
#define G_AL TS32
#define G_WH (2*TS32)
#define G_WL (3*TS32)
#define GEMM_SMEM (8*TS32)

__global__ __launch_bounds__(256, 2) void gemm_tc(
    const ull* __restrict__ A0h, const ull* __restrict__ A0l,
    const ull* __restrict__ W0h, const ull* __restrict__ W0l,
    __nv_bfloat16* __restrict__ C0h, __nv_bfloat16* __restrict__ C0l,
    const ull* __restrict__ A1h, const ull* __restrict__ A1l,
    const ull* __restrict__ W1h_, const ull* __restrict__ W1l_,
    __nv_bfloat16* __restrict__ C1h, __nv_bfloat16* __restrict__ C1l,
    const ull* __restrict__ A2h, const ull* __restrict__ A2l,
    const ull* __restrict__ W2h_, const ull* __restrict__ W2l_,
    __nv_bfloat16* __restrict__ C2h, __nv_bfloat16* __restrict__ C2l)
{
    const ull *Ah, *Al, *Wh, *Wl;
    __nv_bfloat16 *Ch, *Cl;
    if (blockIdx.z == 0)      { Ah=A0h; Al=A0l; Wh=W0h;  Wl=W0l;  Ch=C0h; Cl=C0l; }
    else if (blockIdx.z == 1) { Ah=A1h; Al=A1l; Wh=W1h_; Wl=W1l_; Ch=C1h; Cl=C1l; }
    else                      { Ah=A2h; Al=A2l; Wh=W2h_; Wl=W2l_; Ch=C2h; Cl=C2l; }

    extern __shared__ char smc[];
    const unsigned sbase = smem_u32(smc);
    const int tid = threadIdx.x;
    const int lane = tid & 31;
    const int w = tid >> 5;
    const int wm = w >> 2;
    const int wn = w & 3;
    const int m0 = blockIdx.y * 128;
    const int n0 = blockIdx.x * 128;

    float Ca[16][4];
    #pragma unroll
    for (int nb = 0; nb < 16; nb++)
        #pragma unroll
        for (int r = 0; r < 4; r++) Ca[nb][r] = 0.f;

    const unsigned a_off = (unsigned)((lane & 15) * T32B + (lane >> 4) * 16 + wm * 64 * T32B);
    const unsigned b_off = (unsigned)((((lane >> 4) * 8) + (lane & 7)) * T32B + ((lane >> 3) & 1) * 16
                                      + wn * 32 * T32B);

    const size_t abase = (size_t)m0 * 128;
    const size_t wbase = (size_t)n0 * 128;

    cpa_tile32(sbase + GB32(0) + G_AH, Ah, abase, tid);
    cpa_tile32(sbase + GB32(0) + G_AL, Al, abase, tid);
    cpa_tile32(sbase + GB32(0) + G_WH, Wh, wbase, tid);
    cpa_tile32(sbase + GB32(0) + G_WL, Wl, wbase, tid);
    CPA_COMMIT();

    for (int c = 0; c < 16; c++) {
        if (c < 15) {
            const unsigned nb_ = GB32((c + 1) & 1);
            const size_t ab = abase + (c + 1) * 8;
            const size_t wb = wbase + (c + 1) * 8;
            cpa_tile32(sbase + nb_ + G_AH, Ah, ab, tid);
            cpa_tile32(sbase + nb_ + G_AL, Al, ab, tid);
            cpa_tile32(sbase + nb_ + G_WH, Wh, wb, tid);
            cpa_tile32(sbase + nb_ + G_WL, Wl, wb, tid);
            CPA_COMMIT();
            CPA_WAIT(1);
        } else {
            CPA_WAIT(0);
        }
        __syncthreads();

        const unsigned cb = GB32(c & 1);
        #pragma unroll
        for (int ks = 0; ks < 2; ks++) {
            unsigned ah[4][4], al4[4][4];
            #pragma unroll
            for (int mb = 0; mb < 4; mb++) {
                LDSM4(ah[mb][0], ah[mb][1], ah[mb][2], ah[mb][3],
                      sbase + cb + G_AH + a_off + (unsigned)(mb*16*T32B) + ks*32);
                LDSM4(al4[mb][0], al4[mb][1], al4[mb][2], al4[mb][3],
                      sbase + cb + G_AL + a_off + (unsigned)(mb*16*T32B) + ks*32);
            }
            #pragma unroll
            for (int nb16 = 0; nb16 < 2; nb16++) {
                unsigned bh0,bh1,bh2,bh3, bl0,bl1,bl2,bl3;
                LDSM4(bh0,bh1,bh2,bh3, sbase + cb + G_WH + b_off + (unsigned)(nb16*16*T32B) + ks*32);
                LDSM4(bl0,bl1,bl2,bl3, sbase + cb + G_WL + b_off + (unsigned)(nb16*16*T32B) + ks*32);
                #pragma unroll
                for (int mb = 0; mb < 4; mb++) {
                    MMA_BF16(Ca[mb*4 + nb16*2],     ah[mb], bh0, bh1);
                    MMA_BF16(Ca[mb*4 + nb16*2 + 1], ah[mb], bh2, bh3);
                }
                #pragma unroll
                for (int mb = 0; mb < 4; mb++) {
                    MMA_BF16(Ca[mb*4 + nb16*2],     ah[mb], bl0, bl1);
                    MMA_BF16(Ca[mb*4 + nb16*2 + 1], ah[mb], bl2, bl3);
                }
                #pragma unroll
                for (int mb = 0; mb < 4; mb++) {
                    MMA_BF16(Ca[mb*4 + nb16*2],     al4[mb], bh0, bh1);
                    MMA_BF16(Ca[mb*4 + nb16*2 + 1], al4[mb], bh2, bh3);
                }
            }
        }
        __syncthreads();
    }

    const int g = lane >> 2, t = lane & 3;
    #pragma unroll
    for (int mb = 0; mb < 4; mb++) {
        const int r0 = m0 + wm * 64 + mb * 16 + g;
        const int r1 = r0 + 8;
        #pragma unroll
        for (int nbu = 0; nbu < 4; nbu++) {
            const int col = n0 + wn * 32 + nbu * 8 + 2 * t;
            unsigned h01, l01, h23, l23;
            splitpk(Ca[mb*4+nbu][0], Ca[mb*4+nbu][1], h01, l01);
            splitpk(Ca[mb*4+nbu][2], Ca[mb*4+nbu][3], h23, l23);
            *(unsigned*)&Ch[(size_t)r0 * D_ + col] = h01;
            *(unsigned*)&Cl[(size_t)r0 * D_ + col] = l01;
            *(unsigned*)&Ch[(size_t)r1 * D_ + col] = h23;
            *(unsigned*)&Cl[(size_t)r1 * D_ + col] = l23;
        }
    }
}

// ---------------------------------------------------------------------------
// HMMA attention (round-14 exact): NO-MAX softmax, 2-way j-split, NJT=16,
// BJ=64 double-buffered cp.async, 2 CTAs/SM, K register-persistent.
// ---------------------------------------------------------------------------
#define AQV(buf, t) (2*TSK + (buf)*4*TSQ + (t)*TSQ)
#define ATTN_SMEM (2*TSK + 8*TSQ)
#define NJT 16

__global__ __launch_bounds__(256, 2) void attn_tc(
    const ull* __restrict__ Qh, const ull* __restrict__ Ql,
    const ull* __restrict__ Kh, const ull* __restrict__ Kl,
    const ull* __restrict__ Vh, const ull* __restrict__ Vl,
    float* __restrict__ O0, float* __restrict__ O1,
    float* __restrict__ LS0, float* __restrict__ LS1)
{
    extern __shared__ char smc[];
    const unsigned sbase = smem_u32(smc);
    const int tid = threadIdx.x;
    const int lane = tid & 31;
    const int w = tid >> 5;
    const int it = blockIdx.x;
    const int bh = blockIdx.y;
    const int half = blockIdx.z;
    float* __restrict__ Op  = half ? O1  : O0;
    float* __restrict__ LSp = half ? LS1 : LS0;
    const int b = bh >> 3, h = bh & 7;
    const size_t base = (size_t)b * S_ * D_ + (size_t)h * HD;
    const size_t base4 = base >> 2;
    const int i0 = it * 128;
    const int jt0 = half * NJT;

    cpa_tile<128>(sbase + 0*TSK, Kh, base4 + (size_t)i0 * 128, tid);
    cpa_tile<128>(sbase + 1*TSK, Kl, base4 + (size_t)i0 * 128, tid);
    CPA_COMMIT();
    cpa_tile<64>(sbase + AQV(0,0), Qh, base4 + (size_t)jt0 * 64 * 128, tid);
    cpa_tile<64>(sbase + AQV(0,1), Ql, base4 + (size_t)jt0 * 64 * 128, tid);
    cpa_tile<64>(sbase + AQV(0,2), Vh, base4 + (size_t)jt0 * 64 * 128, tid);
    cpa_tile<64>(sbase + AQV(0,3), Vl, base4 + (size_t)jt0 * 64 * 128, tid);
    CPA_COMMIT();
    CPA_WAIT(1);
    __syncthreads();

    const unsigned a_off = (unsigned)((lane & 15) * TSB + (lane >> 4) * 16) + (unsigned)(w * 16 * TSB);
    unsigned kha[4][4], kla[4][4];
    #pragma unroll
    for (int ks = 0; ks < 4; ks++) {
        LDSM4(kha[ks][0], kha[ks][1], kha[ks][2], kha[ks][3], sbase + 0*TSK + a_off + ks*32);
        LDSM4(kla[ks][0], kla[ks][1], kla[ks][2], kla[ks][3], sbase + 1*TSK + a_off + ks*32);
    }

    const unsigned b_off = (unsigned)((((lane >> 4) * 8) + (lane & 7)) * TSB + ((lane >> 3) & 1) * 16);
    const unsigned v_off = (unsigned)(((((lane >> 3) & 1) * 8) + (lane & 7)) * TSB + (lane >> 4) * 16);

    float Oa[8][4];
    #pragma unroll
    for (int db = 0; db < 8; db++)
        #pragma unroll
        for (int r = 0; r < 4; r++) Oa[db][r] = 0.f;
    float lsum0 = 0.f, lsum1 = 0.f;

    for (int jt = 0; jt < NJT; jt++) {
        if (jt < NJT-1) {
            const int nb_ = (jt + 1) & 1;
            const size_t rb = base4 + (size_t)(jt0 + jt + 1) * 64 * 128;
            cpa_tile<64>(sbase + AQV(nb_,0), Qh, rb, tid);
            cpa_tile<64>(sbase + AQV(nb_,1), Ql, rb, tid);
            cpa_tile<64>(sbase + AQV(nb_,2), Vh, rb, tid);
            cpa_tile<64>(sbase + AQV(nb_,3), Vl, rb, tid);
            CPA_COMMIT();
            CPA_WAIT(1);
        } else {
            CPA_WAIT(0);
        }
        __syncthreads();

        const int bb = jt & 1;
        const unsigned qh_b = sbase + AQV(bb,0);
        const unsigned ql_b = sbase + AQV(bb,1);
        const unsigned vh_b = sbase + AQV(bb,2);
        const unsigned vl_b = sbase + AQV(bb,3);

        float Sa[8][4];
        #pragma unroll
        for (int nb = 0; nb < 8; nb++)
            #pragma unroll
            for (int r = 0; r < 4; r++) Sa[nb][r] = 0.f;

        #pragma unroll
        for (int jp = 0; jp < 2; jp++) {
            #pragma unroll
            for (int ks = 0; ks < 4; ks++) {
                unsigned bh2[2][4], bl2[2][4];
                #pragma unroll
                for (int j = 0; j < 2; j++) {
                    LDSM4(bh2[j][0],bh2[j][1],bh2[j][2],bh2[j][3],
                          qh_b + (unsigned)((jp*2+j)*16*TSB) + ks*32 + b_off);
                    LDSM4(bl2[j][0],bl2[j][1],bl2[j][2],bl2[j][3],
                          ql_b + (unsigned)((jp*2+j)*16*TSB) + ks*32 + b_off);
                }
                #pragma unroll
                for (int j = 0; j < 2; j++) {
                    MMA_BF16(Sa[4*jp+2*j],   kha[ks], bh2[j][0], bh2[j][1]);
                    MMA_BF16(Sa[4*jp+2*j+1], kha[ks], bh2[j][2], bh2[j][3]);
                }
                #pragma unroll
                for (int j = 0; j < 2; j++) {
                    MMA_BF16(Sa[4*jp+2*j],   kha[ks], bl2[j][0], bl2[j][1]);
                    MMA_BF16(Sa[4*jp+2*j+1], kha[ks], bl2[j][2], bl2[j][3]);
                }
                #pragma unroll
                for (int j = 0; j < 2; j++) {
                    MMA_BF16(Sa[4*jp+2*j],   kla[ks], bh2[j][0], bh2[j][1]);
                    MMA_BF16(Sa[4*jp+2*j+1], kla[ks], bh2[j][2], bh2[j][3]);
                }
            }
        }

        float rs0 = 0.f, rs1 = 0.f;
        #pragma unroll
        for (int nb = 0; nb < 8; nb++) {
            Sa[nb][0] = __expf(Sa[nb][0]);
            Sa[nb][1] = __expf(Sa[nb][1]);
            Sa[nb][2] = __expf(Sa[nb][2]);
            Sa[nb][3] = __expf(Sa[nb][3]);
            rs0 += Sa[nb][0] + Sa[nb][1];
            rs1 += Sa[nb][2] + Sa[nb][3];
        }

        unsigned pah[4][4], pal[4][4];
        #pragma unroll
        for (int ks = 0; ks < 4; ks++) {
            splitpk(Sa[2*ks][0],   Sa[2*ks][1],   pah[ks][0], pal[ks][0]);
            splitpk(Sa[2*ks][2],   Sa[2*ks][3],   pah[ks][1], pal[ks][1]);
            splitpk(Sa[2*ks+1][0], Sa[2*ks+1][1], pah[ks][2], pal[ks][2]);
            splitpk(Sa[2*ks+1][2], Sa[2*ks+1][3], pah[ks][3], pal[ks][3]);
        }

        #pragma unroll
        for (int ks = 0; ks < 4; ks++) {
            #pragma unroll
            for (int dp = 0; dp < 2; dp++) {
                unsigned vh[2][4], vl[2][4];
                #pragma unroll
                for (int d = 0; d < 2; d++) {
                    LDSM4T(vh[d][0],vh[d][1],vh[d][2],vh[d][3],
                           vh_b + (unsigned)(ks*16*TSB) + (dp*2+d)*32 + v_off);
                    LDSM4T(vl[d][0],vl[d][1],vl[d][2],vl[d][3],
                           vl_b + (unsigned)(ks*16*TSB) + (dp*2+d)*32 + v_off);
                }
                #pragma unroll
                for (int d = 0; d < 2; d++) {
                    MMA_BF16(Oa[4*dp+2*d],   pah[ks], vh[d][0], vh[d][1]);
                    MMA_BF16(Oa[4*dp+2*d+1], pah[ks], vh[d][2], vh[d][3]);
                }
                #pragma unroll
                for (int d = 0; d < 2; d++) {
                    MMA_BF16(Oa[4*dp+2*d],   pah[ks], vl[d][0], vl[d][1]);
                    MMA_BF16(Oa[4*dp+2*d+1], pah[ks], vl[d][2], vl[d][3]);
                }
                #pragma unroll
                for (int d = 0; d < 2; d++) {
                    MMA_BF16(Oa[4*dp+2*d],   pal[ks], vh[d][0], vh[d][1]);
                    MMA_BF16(Oa[4*dp+2*d+1], pal[ks], vh[d][2], vh[d][3]);
                }
            }
        }

        rs0 += __shfl_xor_sync(0xffffffffu, rs0, 1);
        rs0 += __shfl_xor_sync(0xffffffffu, rs0, 2);
        rs1 += __shfl_xor_sync(0xffffffffu, rs1, 1);
        rs1 += __shfl_xor_sync(0xffffffffu, rs1, 2);
        lsum0 += rs0;
        lsum1 += rs1;
        __syncthreads();
    }

    const int g = lane >> 2, t = lane & 3;
    const int r0 = i0 + w * 16 + g;
    const int r1 = r0 + 8;
    #pragma unroll
    for (int db = 0; db < 8; db++) {
        const int col = db * 8 + 2 * t;
        *(float2*)&Op[base + (size_t)r0 * D_ + col] = make_float2(Oa[db][0], Oa[db][1]);
        *(float2*)&Op[base + (size_t)r1 * D_ + col] = make_float2(Oa[db][2], Oa[db][3]);
    }
    if (t == 0) {
        LSp[bh * S_ + r0] = lsum0;
        LSp[bh * S_ + r1] = lsum1;
    }
}

// ---------------------------------------------------------------------------
extern "C" void kernel_launch(void* const* d_in, const int* in_sizes, int n_in,
                              void* d_out, int out_size)
{
    const float* seq_k = (const float*)d_in[0];
    const float* seq_q = (const float*)d_in[1];
    const float* seq_v = (const float*)d_in[2];
    const float* W1    = (const float*)d_in[3];
    const float* W2    = (const float*)d_in[4];
    const float* W3    = (const float*)d_in[5];
    const float* gamma = (const float*)d_in[6];
    const float* beta  = (const float*)d_in[7];
    float* out = (float*)d_out;

    float *vin, *att0, *att1, *ls0, *ls1;
    ull *sqh,*sql,*skh,*skl,*svh,*svl,*w1h,*w1l,*w2h,*w2l,*w3h,*w3l;
    ull *qh,*ql,*kh,*kl,*vh,*vl;
    cudaGetSymbolAddress((void**)&vin,  g_vin);
    cudaGetSymbolAddress((void**)&att0, g_att0);
    cudaGetSymbolAddress((void**)&att1, g_att1);
    cudaGetSymbolAddress((void**)&ls0,  g_ls0);
    cudaGetSymbolAddress((void**)&ls1,  g_ls1);
    cudaGetSymbolAddress((void**)&sqh, g_sqh); cudaGetSymbolAddress((void**)&sql, g_sql);
    cudaGetSymbolAddress((void**)&skh, g_skh); cudaGetSymbolAddress((void**)&skl, g_skl);
    cudaGetSymbolAddress((void**)&svh, g_svh); cudaGetSymbolAddress((void**)&svl, g_svl);
    cudaGetSymbolAddress((void**)&w1h, g_w1h); cudaGetSymbolAddress((void**)&w1l, g_w1l);
    cudaGetSymbolAddress((void**)&w2h, g_w2h); cudaGetSymbolAddress((void**)&w2l, g_w2l);
    cudaGetSymbolAddress((void**)&w3h, g_w3h); cudaGetSymbolAddress((void**)&w3l, g_w3l);
    cudaGetSymbolAddress((void**)&qh,  g_qh);  cudaGetSymbolAddress((void**)&ql,  g_ql);
    cudaGetSymbolAddress((void**)&kh,  g_kh);  cudaGetSymbolAddress((void**)&kl,  g_kl);
    cudaGetSymbolAddress((void**)&vh,  g_vh);  cudaGetSymbolAddress((void**)&vl,  g_vl);

    // 1) merged prologue
    prologue_kernel<<<6336, 256>>>(
        seq_v, gamma, beta, vin, svh, svl,
        (const float4*)seq_q, sqh, sql,
        (const float4*)seq_k, skh, skl,
        (const float4*)W1, w1h, w1l,
        (const float4*)W2, w2h, w2l,
        (const float4*)W3, w3h, w3l);

    // 2) projections
    cudaFuncSetAttribute(gemm_tc, cudaFuncAttributeMaxDynamicSharedMemorySize, GEMM_SMEM);
    dim3 ggrid(D_ / 128, M_ / 128, 3);
    gemm_tc<<<ggrid, 256, GEMM_SMEM>>>(
        sqh, sql, w1h, w1l, (__nv_bfloat16*)qh, (__nv_bfloat16*)ql,
        skh, skl, w2h, w2l, (__nv_bfloat16*)kh, (__nv_bfloat16*)kl,
        svh, svl, w3h, w3l, (__nv_bfloat16*)vh, (__nv_bfloat16*)vl);

    // 3) attention (2-way j-split)
    cudaFuncSetAttribute(attn_tc, cudaFuncAttributeMaxDynamicSharedMemorySize, ATTN_SMEM);
    attn_tc<<<dim3(S_ / 128, B_ * H_, 2), 256, ATTN_SMEM>>>(qh, ql, kh, kl, vh, vl,
                                                            att0, att1, ls0, ls1);

    // 4) combine + residual + final LN (2 rows/block)
    ln_final_kernel<<<M_/2, 256>>>(att0, att1, ls0, ls1, vin, gamma, beta, out);
}